// round 16
// baseline (speedup 1.0000x reference)
#include <cuda_runtime.h>
#include <cuda_bf16.h>

// Problem constants (WordSmoothCriterion: B=4, T=2048, V=32000, NNZ=801)
#define NROWS 8192
#define VDIM  32000
#define NNZ   801
#define TAU   0.8f
#define RARE  1.0f
#define ALPHA 0.7f

#define TPB  256
#define EPT  4          // 4*256 = 1024 >= 801 (k=3 slice predicated: tid < 33)
#define GRID 740        // 148 SMs * 5 resident CTAs -> single persistent wave

// Scratch (device globals — allocation-free)
__device__ float g_smooth[NROWS];      // per-row sum(g*sim)
__device__ float g_ml[NROWS];          // per-row lp[target]*mask
__device__ float g_maskv[NROWS];       // per-row mask
__device__ unsigned int g_work  = 0;   // work cursor (self-resetting)
__device__ unsigned int g_count = 0;   // completion counter (self-resetting)

// ---------------------------------------------------------------------------
// Persistent pipelined kernel with CLAIM-AHEAD work stealing.
// The atomic claim for row i+2 is issued at iteration i and consumed at
// iteration i+1 (visibility via iteration i's reduction barriers) -> claim
// latency fully hidden, unlike R11's exposed claim.
// Per-row output slots + fixed-order final reduce -> bitwise deterministic.
// ---------------------------------------------------------------------------
__global__ __launch_bounds__(TPB, 5)
void ws_ca_kernel(const float* __restrict__ logp,
                  const float* __restrict__ mask,
                  const float* __restrict__ sim_values,
                  const float* __restrict__ idf_values,
                  const int*   __restrict__ target,
                  const int*   __restrict__ sim_cols,
                  float*       __restrict__ out)
{
    const int tid  = threadIdx.x;
    const int warp = tid >> 5;
    const int lane = tid & 31;
    const float inv_tau = 1.0f / TAU;
    const bool p3 = (tid < NNZ - 3 * TPB);      // k=3 slice predicate (tid < 33)

    __shared__ float s_v[8], s_gv[8];
    __shared__ int   s_claim[2];                // double-buffered prefetched claims
    __shared__ bool  s_last;

    // ---------------- prologue: claim rows 0 and 1, load row 0 ----------------
    if (tid == 0) {
        s_claim[0] = (int)atomicAdd(&g_work, 1u);   // row A (always < NROWS: GRID<=NROWS)
        s_claim[1] = (int)atomicAdd(&g_work, 1u);   // row B
    }
    __syncthreads();
    int nA = s_claim[0];
    int nB = s_claim[1];

    int   cA[EPT];
    float sA[EPT], dA[EPT], gA[EPT];
    float mA = 0.0f, lprA = 0.0f;
    {
        const int rA = target[nA];
        const float* lpA = logp       + (size_t)nA * VDIM;
        const float* svA = sim_values + (size_t)rA * NNZ;
        const float* ivA = idf_values + (size_t)rA * NNZ;
        const int*   scA = sim_cols   + (size_t)rA * NNZ;
        #pragma unroll
        for (int k = 0; k < EPT; k++) {
            const bool ok = (k < 3) || p3;
            const int  j  = tid + k * TPB;
            cA[k] = ok ? scA[j] : 0;
            sA[k] = ok ? svA[j] : 0.0f;
            dA[k] = ok ? ivA[j] : 0.0f;
        }
        if (tid == 0) { mA = mask[nA]; lprA = lpA[rA]; }
        #pragma unroll
        for (int k = 0; k < EPT; k++) gA[k] = lpA[cA[k]];
    }

    // ---------------- main pipelined loop ----------------
    int it = 0;
    while (nA < NROWS) {
        const int  wslot = it & 1;
        const bool hb    = (nB < NROWS);

        // 0. prefetch the claim for the iteration after this one (no barrier;
        //    becomes visible through this iteration's reduction barriers)
        if (tid == 0) s_claim[wslot] = (int)atomicAdd(&g_work, 1u);

        // 1. issue next row's index/value loads
        int   cB[EPT];
        float sB[EPT], dB[EPT];
        float mB = 0.0f, lprB = 0.0f;
        const float* lpB = logp;                 // safe default
        if (hb) {
            const int rB = target[nB];
            lpB = logp + (size_t)nB * VDIM;
            const float* svB = sim_values + (size_t)rB * NNZ;
            const float* ivB = idf_values + (size_t)rB * NNZ;
            const int*   scB = sim_cols   + (size_t)rB * NNZ;
            #pragma unroll
            for (int k = 0; k < EPT; k++) {
                const bool ok = (k < 3) || p3;
                const int  j  = tid + k * TPB;
                cB[k] = ok ? scB[j] : 0;
                sB[k] = ok ? svB[j] : 0.0f;
                dB[k] = ok ? ivB[j] : 0.0f;
            }
            if (tid == 0) { mB = mask[nB]; lprB = lpB[rB]; }
        } else {
            #pragma unroll
            for (int k = 0; k < EPT; k++) { cB[k] = 0; sB[k] = 0.0f; dB[k] = 0.0f; }
        }

        // 2. compute current row
        float sum_v = 0.0f, sum_gv = 0.0f;
        #pragma unroll
        for (int k = 0; k < EPT; k++) {
            const bool ok = (k < 3) || p3;
            float val = __expf(__expf((sA[k] - 1.0f - TAU * RARE * dA[k]) * inv_tau) * inv_tau);
            if (!ok) val = 0.0f;
            sum_v  += val;
            sum_gv += val * gA[k];
        }

        // 3. issue next row's gathers (in flight during the reduction)
        float gB[EPT];
        if (hb) {
            #pragma unroll
            for (int k = 0; k < EPT; k++) gB[k] = lpB[cB[k]];
        } else {
            #pragma unroll
            for (int k = 0; k < EPT; k++) gB[k] = 0.0f;
        }

        // 4. block reduction of (sum_v, sum_gv)
        #pragma unroll
        for (int o = 16; o > 0; o >>= 1) {
            sum_v  += __shfl_down_sync(0xffffffffu, sum_v,  o);
            sum_gv += __shfl_down_sync(0xffffffffu, sum_gv, o);
        }
        if (lane == 0) { s_v[warp] = sum_v; s_gv[warp] = sum_gv; }
        __syncthreads();
        if (warp == 0) {
            float a = (lane < 8) ? s_v[lane]  : 0.0f;
            float b = (lane < 8) ? s_gv[lane] : 0.0f;
            #pragma unroll
            for (int o = 4; o > 0; o >>= 1) {
                a += __shfl_down_sync(0xffffffffu, a, o);
                b += __shfl_down_sync(0xffffffffu, b, o);
            }
            if (lane == 0) {
                g_smooth[nA] = b / a;            // per-row slots -> deterministic
                g_ml[nA]     = lprA * mA;
                g_maskv[nA]  = mA;
            }
        }
        __syncthreads();                         // protects s_v/s_gv AND publishes s_claim[wslot]

        // 5. rotate pipeline (claim prefetched at step 0, now visible)
        nA = nB;
        nB = s_claim[wslot];
        mA = mB; lprA = lprB;
        #pragma unroll
        for (int k = 0; k < EPT; k++) {
            cA[k] = cB[k]; sA[k] = sB[k]; dA[k] = dB[k]; gA[k] = gB[k];
        }
        it++;
    }

    // ---------------- completion + last-CTA final reduction ----------------
    if (tid == 0) {
        __threadfence();
        unsigned int old = atomicAdd(&g_count, 1u);
        s_last = (old == (unsigned int)(GRID - 1));
    }
    __syncthreads();

    if (s_last) {
        double d_sm = 0.0, d_ml = 0.0, d_m = 0.0;
        for (int i = tid; i < NROWS; i += TPB) { // fixed row order -> deterministic
            d_sm += (double)g_smooth[i];
            d_ml += (double)g_ml[i];
            d_m  += (double)g_maskv[i];
        }
        #pragma unroll
        for (int o = 16; o > 0; o >>= 1) {
            d_sm += __shfl_down_sync(0xffffffffu, d_sm, o);
            d_ml += __shfl_down_sync(0xffffffffu, d_ml, o);
            d_m  += __shfl_down_sync(0xffffffffu, d_m,  o);
        }
        __shared__ double sh[3][8];
        if (lane == 0) { sh[0][warp] = d_sm; sh[1][warp] = d_ml; sh[2][warp] = d_m; }
        __syncthreads();
        if (warp == 0) {
            d_sm = (lane < 8) ? sh[0][lane] : 0.0;
            d_ml = (lane < 8) ? sh[1][lane] : 0.0;
            d_m  = (lane < 8) ? sh[2][lane] : 0.0;
            #pragma unroll
            for (int o = 4; o > 0; o >>= 1) {
                d_sm += __shfl_down_sync(0xffffffffu, d_sm, o);
                d_ml += __shfl_down_sync(0xffffffffu, d_ml, o);
                d_m  += __shfl_down_sync(0xffffffffu, d_m,  o);
            }
            if (lane == 0) {
                double smooth_loss = -d_sm / d_m;
                double ml_loss     = -d_ml / d_m;
                out[0] = (float)((double)ALPHA * smooth_loss
                                 + (1.0 - (double)ALPHA) * ml_loss);
                g_count = 0;                     // reset for next graph replay
                g_work  = 0;
            }
        }
    }
}

// ---------------------------------------------------------------------------
extern "C" void kernel_launch(void* const* d_in, const int* in_sizes, int n_in,
                              void* d_out, int out_size)
{
    const float* logp       = (const float*)d_in[0];
    const float* mask       = (const float*)d_in[1];
    const float* sim_values = (const float*)d_in[2];
    const float* idf_values = (const float*)d_in[3];
    const int*   target     = (const int*)  d_in[4];
    const int*   sim_cols   = (const int*)  d_in[5];
    float*       out        = (float*)d_out;

    ws_ca_kernel<<<GRID, TPB>>>(logp, mask, sim_values, idf_values,
                                target, sim_cols, out);
}

// round 17
// speedup vs baseline: 1.1145x; 1.1145x over previous
#include <cuda_runtime.h>
#include <cuda_bf16.h>

// Problem constants (WordSmoothCriterion: B=4, T=2048, V=32000, NNZ=801)
#define NROWS 8192
#define VDIM  32000
#define NNZ   801
#define TAU   0.8f
#define RARE  1.0f
#define ALPHA 0.7f

#define TPB  256
#define EPT  4          // 4*256 = 1024 >= 801 (k=3 slice predicated: tid < 33)
#define GRID 592        // 148 SMs * 4 resident CTAs -> single persistent wave

// Scratch (device globals — allocation-free)
__device__ double g_psm[GRID];
__device__ double g_pml[GRID];
__device__ double g_pm[GRID];
__device__ unsigned int g_count = 0;   // completion counter (self-resetting)

// ---------------------------------------------------------------------------
// R9 persistent pipelined kernel with ONE barrier per row (double-buffered
// reduction smem: iteration i writes buffer i&1; after the sync, warp 0 reads
// buffer i&1 while the other warps may already write buffer (i+1)&1 next
// iteration -> no overwrite hazard, trailing barrier removed).
// ---------------------------------------------------------------------------
__global__ __launch_bounds__(TPB, 5)
void ws_persist_kernel(const float* __restrict__ logp,
                       const float* __restrict__ mask,
                       const float* __restrict__ sim_values,
                       const float* __restrict__ idf_values,
                       const int*   __restrict__ target,
                       const int*   __restrict__ sim_cols,
                       float*       __restrict__ out)
{
    const int bid  = blockIdx.x;
    const int tid  = threadIdx.x;
    const int warp = tid >> 5;
    const int lane = tid & 31;
    const float inv_tau = 1.0f / TAU;
    const bool p3 = (tid < NNZ - 3 * TPB);      // k=3 slice predicate (tid < 33)

    __shared__ float s_v[2][8], s_gv[2][8];     // double-buffered per-warp partials
    __shared__ bool  s_last;

    // per-CTA accumulators (only warp0/lane0 updates; fixed order -> deterministic)
    double acc_sm = 0.0, acc_ml = 0.0, acc_m = 0.0;

    // ---------------- prologue: load row n = bid ----------------
    int n  = bid;
    int it = 0;
    const float* lpA = logp + (size_t)n * VDIM;
    int   cA[EPT];
    float sA[EPT], dA[EPT], gA[EPT];
    float mA = 0.0f, lprA = 0.0f;
    {
        const int rA = target[n];
        const float* svA = sim_values + (size_t)rA * NNZ;
        const float* ivA = idf_values + (size_t)rA * NNZ;
        const int*   scA = sim_cols   + (size_t)rA * NNZ;
        #pragma unroll
        for (int k = 0; k < EPT; k++) {
            const bool ok = (k < 3) || p3;
            const int  j  = tid + k * TPB;
            cA[k] = ok ? scA[j] : 0;
            sA[k] = ok ? svA[j] : 0.0f;
            dA[k] = ok ? ivA[j] : 0.0f;
        }
        if (tid == 0) { mA = mask[n]; lprA = lpA[rA]; }
        #pragma unroll
        for (int k = 0; k < EPT; k++) gA[k] = lpA[cA[k]];
    }

    // ---------------- main pipelined loop ----------------
    while (true) {
        const int  n2 = n + GRID;
        const bool hn = (n2 < NROWS);
        const int  buf = it & 1;

        // ---- issue next row's index/value loads ----
        int   cB[EPT];
        float sB[EPT], dB[EPT];
        float mB = 0.0f, lprB = 0.0f;
        const float* lpB = logp;                 // safe default
        if (hn) {
            lpB = logp + (size_t)n2 * VDIM;
            const int rB = target[n2];
            const float* svB = sim_values + (size_t)rB * NNZ;
            const float* ivB = idf_values + (size_t)rB * NNZ;
            const int*   scB = sim_cols   + (size_t)rB * NNZ;
            #pragma unroll
            for (int k = 0; k < EPT; k++) {
                const bool ok = (k < 3) || p3;
                const int  j  = tid + k * TPB;
                cB[k] = ok ? scB[j] : 0;
                sB[k] = ok ? svB[j] : 0.0f;
                dB[k] = ok ? ivB[j] : 0.0f;
            }
            if (tid == 0) { mB = mask[n2]; lprB = lpB[rB]; }
        } else {
            #pragma unroll
            for (int k = 0; k < EPT; k++) { cB[k] = 0; sB[k] = 0.0f; dB[k] = 0.0f; }
        }

        // ---- compute current row ----
        float sum_v = 0.0f, sum_gv = 0.0f;
        #pragma unroll
        for (int k = 0; k < EPT; k++) {
            const bool ok = (k < 3) || p3;
            float val = __expf(__expf((sA[k] - 1.0f - TAU * RARE * dA[k]) * inv_tau) * inv_tau);
            if (!ok) val = 0.0f;
            sum_v  += val;
            sum_gv += val * gA[k];
        }

        // ---- issue next row's gathers (in flight during the reduction) ----
        float gB[EPT];
        if (hn) {
            #pragma unroll
            for (int k = 0; k < EPT; k++) gB[k] = lpB[cB[k]];
        } else {
            #pragma unroll
            for (int k = 0; k < EPT; k++) gB[k] = 0.0f;
        }

        // ---- reduction: single barrier per row (double-buffered smem) ----
        #pragma unroll
        for (int o = 16; o > 0; o >>= 1) {
            sum_v  += __shfl_down_sync(0xffffffffu, sum_v,  o);
            sum_gv += __shfl_down_sync(0xffffffffu, sum_gv, o);
        }
        if (lane == 0) { s_v[buf][warp] = sum_v; s_gv[buf][warp] = sum_gv; }
        __syncthreads();                        // publish buffer `buf`
        if (warp == 0) {
            float a = (lane < 8) ? s_v[buf][lane]  : 0.0f;
            float b = (lane < 8) ? s_gv[buf][lane] : 0.0f;
            #pragma unroll
            for (int o = 4; o > 0; o >>= 1) {
                a += __shfl_down_sync(0xffffffffu, a, o);
                b += __shfl_down_sync(0xffffffffu, b, o);
            }
            if (lane == 0) {
                acc_sm += (double)(b / a);
                acc_ml += (double)(lprA * mA);
                acc_m  += (double)mA;
            }
        }
        // no trailing barrier: next iteration writes buffer buf^1

        if (!hn) break;

        // ---- rotate pipeline ----
        n   = n2;
        lpA = lpB; mA = mB; lprA = lprB;
        #pragma unroll
        for (int k = 0; k < EPT; k++) {
            cA[k] = cB[k]; sA[k] = sB[k]; dA[k] = dB[k]; gA[k] = gB[k];
        }
        it++;
    }

    __syncthreads();                            // all warps done before epilogue

    // ---------------- write per-CTA partials, last CTA finishes ----------------
    if (tid == 0) {
        g_psm[bid] = acc_sm;
        g_pml[bid] = acc_ml;
        g_pm[bid]  = acc_m;
        __threadfence();
        unsigned int old = atomicAdd(&g_count, 1u);
        s_last = (old == (unsigned int)(GRID - 1));
    }
    __syncthreads();

    if (s_last) {
        double d_sm = 0.0, d_ml = 0.0, d_m = 0.0;
        for (int i = tid; i < GRID; i += TPB) {   // fixed order -> deterministic
            d_sm += g_psm[i];
            d_ml += g_pml[i];
            d_m  += g_pm[i];
        }
        #pragma unroll
        for (int o = 16; o > 0; o >>= 1) {
            d_sm += __shfl_down_sync(0xffffffffu, d_sm, o);
            d_ml += __shfl_down_sync(0xffffffffu, d_ml, o);
            d_m  += __shfl_down_sync(0xffffffffu, d_m,  o);
        }
        __shared__ double sh[3][8];
        if (lane == 0) { sh[0][warp] = d_sm; sh[1][warp] = d_ml; sh[2][warp] = d_m; }
        __syncthreads();
        if (warp == 0) {
            d_sm = (lane < 8) ? sh[0][lane] : 0.0;
            d_ml = (lane < 8) ? sh[1][lane] : 0.0;
            d_m  = (lane < 8) ? sh[2][lane] : 0.0;
            #pragma unroll
            for (int o = 4; o > 0; o >>= 1) {
                d_sm += __shfl_down_sync(0xffffffffu, d_sm, o);
                d_ml += __shfl_down_sync(0xffffffffu, d_ml, o);
                d_m  += __shfl_down_sync(0xffffffffu, d_m,  o);
            }
            if (lane == 0) {
                double smooth_loss = -d_sm / d_m;
                double ml_loss     = -d_ml / d_m;
                out[0] = (float)((double)ALPHA * smooth_loss
                                 + (1.0 - (double)ALPHA) * ml_loss);
                g_count = 0;   // reset for next graph replay
            }
        }
    }
}

// ---------------------------------------------------------------------------
extern "C" void kernel_launch(void* const* d_in, const int* in_sizes, int n_in,
                              void* d_out, int out_size)
{
    const float* logp       = (const float*)d_in[0];
    const float* mask       = (const float*)d_in[1];
    const float* sim_values = (const float*)d_in[2];
    const float* idf_values = (const float*)d_in[3];
    const int*   target     = (const int*)  d_in[4];
    const int*   sim_cols   = (const int*)  d_in[5];
    float*       out        = (float*)d_out;

    ws_persist_kernel<<<GRID, TPB>>>(logp, mask, sim_values, idf_values,
                                     target, sim_cols, out);
}